// round 2
// baseline (speedup 1.0000x reference)
#include <cuda_runtime.h>
#include <cuda_bf16.h>

// Problem constants (fixed by setup_inputs): B=8, N=128, T=1024, K=3
#define BB   8
#define NN   128
#define TT   1024
#define VPAD 1152   // T + N - 1 = 1151, rounded up (zero-padded tail)

__device__ float g_stdv[BB * VPAD];

__global__ void prep_std_kernel(const float* __restrict__ k) {
    int idx = blockIdx.x * blockDim.x + threadIdx.x;
    if (idx >= BB * VPAD) return;
    int b = idx / VPAD;
    int t = idx - b * VPAD;
    float v = 0.0f;
    if (t < TT) {
        // v[b,t] = k_gp[b,b,0,t]
        size_t off = ((size_t)(b * BB + b) * NN * TT + t) * 2;
        v = k[off];
    }
    g_stdv[idx] = sqrtf(fmaxf(v, 0.0f));
}

__global__ __launch_bounds__(256) void fused_arc_conv_kernel(
    const float* __restrict__ k,
    const float* __restrict__ leak,
    const float* __restrict__ alpha,
    const float* __restrict__ beta,
    float* __restrict__ out)
{
    __shared__ __align__(16) float s0[TT + 4];
    __shared__ __align__(16) float s1[TT + 4];

    const int row = blockIdx.x;          // 0 .. B*B*N-1, layout (i,j,n)
    const int n   = row & (NN - 1);
    const int ij  = row >> 7;
    const int j   = ij & (BB - 1);
    const int i   = ij >> 3;

    const float a  = fmaxf(leak[0], 0.0f);
    const float w0 = fmaxf(alpha[0], 0.0f);
    const float w1 = fmaxf(alpha[1], 0.0f);
    const float w2 = fmaxf(alpha[2], 0.0f);
    const float bv = fmaxf(beta[0], 0.0f);

    const float PIf      = 3.14159265358979323846f;
    const float one_m    = (1.0f - a) * (1.0f - a);
    const float coef     = 1.0f + a * a;
    const float halfcoef = 0.5f * coef;
    const float inv2pi   = 1.0f / (2.0f * PIf);
    const float RL       = 1.0f - 1e-6f;
    const float EPS      = 1e-12f;

    const int tid = threadIdx.x;
    const int t4  = tid * 4;

    const float4* __restrict__ krow4 = reinterpret_cast<const float4*>(k) + (size_t)row * (TT / 2);
    float4* __restrict__ orow4       = reinterpret_cast<float4*>(out)     + (size_t)row * (TT / 2);
    const float* __restrict__ sx = g_stdv + i * VPAD;       // std_x[t]
    const float* __restrict__ sy = g_stdv + j * VPAD + n;   // std_y[t] = stdv[j, n+t]

    // ---- load 4 points (vectorized) ----
    const float4 ka  = krow4[tid * 2];       // points t4, t4+1 : (gp,ntk,gp,ntk)
    const float4 kb  = krow4[tid * 2 + 1];   // points t4+2, t4+3
    const float4 sxv = *reinterpret_cast<const float4*>(sx + t4);  // aligned: t4%4==0, VPAD%4==0

    float kgp[4] = {ka.x, ka.z, kb.x, kb.z};
    float knt[4] = {ka.y, ka.w, kb.y, kb.w};
    float sxa[4] = {sxv.x, sxv.y, sxv.z, sxv.w};
    float sya[4] = {sy[t4], sy[t4 + 1], sy[t4 + 2], sy[t4 + 3]};

    float c0q[4], c1q[4];

    if (one_m == 0.0f) {
        // leak == 1: theta/s terms vanish analytically.
        // c0 = halfcoef * sxy * clamp(kgp/max(sxy,EPS), +-RL) == halfcoef * clamp(kgp, +-RL*sxy)
        // c1 = halfcoef
        #pragma unroll
        for (int q = 0; q < 4; ++q) {
            const float sxy = sxa[q] * sya[q];
            const float lim = RL * sxy;
            c0q[q] = halfcoef * fminf(fmaxf(kgp[q], -lim), lim);
            c1q[q] = halfcoef * knt[q];
        }
    } else {
        // general path (kept for arbitrary leak); not taken for this input
        #pragma unroll 1
        for (int q = 0; q < 4; ++q) {
            const float sxy   = sxa[q] * sya[q];
            const float denom = fmaxf(sxy, EPS);
            float rho = fminf(fmaxf(kgp[q] / denom, -RL), RL);
            const float theta = acosf(rho);
            const float s     = sqrtf(fmaxf(1.0f - rho * rho, 0.0f));
            const float tpart = coef * PIf - one_m * theta;
            c0q[q] = sxy * inv2pi * (one_m * s + rho * tpart);
            c1q[q] = tpart * inv2pi * knt[q];
        }
    }

    *reinterpret_cast<float4*>(&s0[t4]) = make_float4(c0q[0], c0q[1], c0q[2], c0q[3]);
    *reinterpret_cast<float4*>(&s1[t4]) = make_float4(c1q[0], c1q[1], c1q[2], c1q[3]);
    if (tid == 0) { s0[TT] = 0.0f; s1[TT] = 0.0f; }
    __syncthreads();

    // ---- 3-tap conv: 4 center taps already in registers; only halos from smem ----
    const float l0 = (tid == 0) ? 0.0f : s0[t4 - 1];
    const float r0 = s0[t4 + 4];
    const float l1 = (tid == 0) ? 0.0f : s1[t4 - 1];
    const float r1 = s1[t4 + 4];

    const float kg0 = w0 * l0     + w1 * c0q[0] + w2 * c0q[1];
    const float kg1 = w0 * c0q[0] + w1 * c0q[1] + w2 * c0q[2];
    const float kg2 = w0 * c0q[1] + w1 * c0q[2] + w2 * c0q[3];
    const float kg3 = w0 * c0q[2] + w1 * c0q[3] + w2 * r0;

    const float kn0 = w0 * l1     + w1 * c1q[0] + w2 * c1q[1] + kg0;
    const float kn1 = w0 * c1q[0] + w1 * c1q[1] + w2 * c1q[2] + kg1;
    const float kn2 = w0 * c1q[1] + w1 * c1q[2] + w2 * c1q[3] + kg2;
    const float kn3 = w0 * c1q[2] + w1 * c1q[3] + w2 * r1     + kg3;

    orow4[tid * 2]     = make_float4(kg0 + bv, kn0 + bv, kg1 + bv, kn1 + bv);
    orow4[tid * 2 + 1] = make_float4(kg2 + bv, kn2 + bv, kg3 + bv, kn3 + bv);
}

extern "C" void kernel_launch(void* const* d_in, const int* in_sizes, int n_in,
                              void* d_out, int out_size) {
    const float* k     = (const float*)d_in[0];
    const float* leak  = (const float*)d_in[1];
    const float* alpha = (const float*)d_in[2];
    const float* beta  = (const float*)d_in[3];
    float* out = (float*)d_out;

    prep_std_kernel<<<(BB * VPAD + 255) / 256, 256>>>(k);
    fused_arc_conv_kernel<<<BB * BB * NN, 256>>>(k, leak, alpha, beta, out);
}